// round 14
// baseline (speedup 1.0000x reference)
#include <cuda_runtime.h>
#include <cuda_bf16.h>
#include <stdint.h>
#include <math.h>

#define TOKENS 4096
#define DIM    2048
#define NEXP   32
#define TOPK   8
#define MDIM   768
#define NROWS  (TOKENS*TOPK)
#define BM     128
#define MAX_TILES 288

__device__ __forceinline__ uint32_t smem_u32(const void* p) {
    uint32_t a;
    asm("{ .reg .u64 t; cvta.to.shared.u64 t, %1; cvt.u32.u64 %0, t; }" : "=r"(a) : "l"(p));
    return a;
}

#define LDSM4(r, addr) \
    asm volatile("ldmatrix.sync.aligned.m8n8.x4.shared.b16 {%0,%1,%2,%3}, [%4];" \
        : "=r"((r)[0]), "=r"((r)[1]), "=r"((r)[2]), "=r"((r)[3]) : "r"(addr))

#define LDSM4T(r, addr) \
    asm volatile("ldmatrix.sync.aligned.m8n8.x4.trans.shared.b16 {%0,%1,%2,%3}, [%4];" \
        : "=r"((r)[0]), "=r"((r)[1]), "=r"((r)[2]), "=r"((r)[3]) : "r"(addr))

#define MMA_BF16(d, a, b0v, b1v) \
    asm volatile("mma.sync.aligned.m16n8k16.row.col.f32.bf16.bf16.f32 " \
        "{%0,%1,%2,%3},{%4,%5,%6,%7},{%8,%9},{%0,%1,%2,%3};" \
        : "+f"((d)[0]), "+f"((d)[1]), "+f"((d)[2]), "+f"((d)[3]) \
        : "r"((a)[0]), "r"((a)[1]), "r"((a)[2]), "r"((a)[3]), "r"(b0v), "r"(b1v))

__device__ __forceinline__ void split2(float v, __nv_bfloat16& h, __nv_bfloat16& l) {
    h = __float2bfloat16(v);
    l = __float2bfloat16(v - __bfloat162float(h));
}
__device__ __forceinline__ uint32_t pack2(__nv_bfloat16 a, __nv_bfloat16 b) {
    __nv_bfloat162 t(a, b);
    return *(uint32_t*)&t;
}
// RN split (activations)
__device__ __forceinline__ void split4pack(float4 v, uint2& hh, uint2& ll) {
    __nv_bfloat16 h0, h1, h2, h3, l0, l1, l2, l3;
    split2(v.x, h0, l0); split2(v.y, h1, l1);
    split2(v.z, h2, l2); split2(v.w, h3, l3);
    hh = make_uint2(pack2(h0, h1), pack2(h2, h3));
    ll = make_uint2(pack2(l0, l1), pack2(l2, l3));
}
// Truncation split (weights): hi = top-16 bits, lo = RN bf16 of residual
__device__ __forceinline__ void split4pack_trunc(float4 v, uint2& hh, uint2& ll) {
    uint32_t x0 = __float_as_uint(v.x), x1 = __float_as_uint(v.y);
    uint32_t x2 = __float_as_uint(v.z), x3 = __float_as_uint(v.w);
    hh.x = __byte_perm(x0, x1, 0x7632);
    hh.y = __byte_perm(x2, x3, 0x7632);
    float l0 = v.x - __uint_as_float(x0 & 0xffff0000u);
    float l1 = v.y - __uint_as_float(x1 & 0xffff0000u);
    float l2 = v.z - __uint_as_float(x2 & 0xffff0000u);
    float l3 = v.w - __uint_as_float(x3 & 0xffff0000u);
    uint32_t p0, p1;
    asm("cvt.rn.bf16x2.f32 %0, %1, %2;" : "=r"(p0) : "f"(l1), "f"(l0));
    asm("cvt.rn.bf16x2.f32 %0, %1, %2;" : "=r"(p1) : "f"(l3), "f"(l2));
    ll = make_uint2(p0, p1);
}

// ============ device scratch (~402MB, proven budget) ============
__device__ int   g_off[NEXP + 1];
__device__ int   g_expert_of[NROWS];
__device__ float g_weight_of[NROWS];
__device__ int   g_row_token[NROWS];
__device__ int   g_pos_of[NROWS];
__device__ int   g_tile_expert[MAX_TILES];
__device__ int   g_tile_row[MAX_TILES];
__device__ int   g_num_tiles;
__device__ __nv_bfloat16 g_Xh[(size_t)TOKENS * DIM];
__device__ __nv_bfloat16 g_Xl[(size_t)TOKENS * DIM];
__device__ __nv_bfloat16 g_Ih[(size_t)NROWS * MDIM];
__device__ __nv_bfloat16 g_Il[(size_t)NROWS * MDIM];
__device__ float g_eout[(size_t)NROWS * DIM];

// ============ token fp32 -> split bf16 (launch #1) ============
__global__ __launch_bounds__(256) void k_convert_x(const float* __restrict__ x) {
    int t = blockIdx.x;
    const float4* src = (const float4*)(x + (size_t)t * DIM);
#pragma unroll
    for (int i = 0; i < 2; i++) {
        int idx = threadIdx.x + i * 256;
        uint2 hh, ll;
        split4pack(src[idx], hh, ll);
        *(uint2*)(g_Xh + (size_t)t * DIM + idx * 4) = hh;
        *(uint2*)(g_Xl + (size_t)t * DIM + idx * 4) = ll;
    }
}

// ============ router (launch #2) ============
__global__ __launch_bounds__(256) void k_router(const float* __restrict__ x,
                                                const float* __restrict__ gk) {
    __shared__ float xs[64][64];
    __shared__ float gs[64][32];
    __shared__ float lg[64][32];
    int tid = threadIdx.x, t0 = blockIdx.x * 64, e = tid & 31, r8 = tid >> 5;
    float acc[8];
#pragma unroll
    for (int i = 0; i < 8; i++) acc[i] = 0.f;
    for (int d0 = 0; d0 < DIM; d0 += 64) {
#pragma unroll
        for (int i = 0; i < 4; i++) {
            int f = tid + i * 256, row = f >> 4, dv = f & 15;
            *(float4*)&xs[row][dv * 4] =
                *(const float4*)(x + (size_t)(t0 + row) * DIM + d0 + dv * 4);
        }
#pragma unroll
        for (int i = 0; i < 2; i++) {
            int f = tid + i * 256, dd = f >> 3, ev = f & 7;
            *(float4*)&gs[dd][ev * 4] =
                *(const float4*)(gk + (size_t)(d0 + dd) * NEXP + ev * 4);
        }
        __syncthreads();
#pragma unroll 8
        for (int dd = 0; dd < 64; dd++) {
            float g = gs[dd][e];
#pragma unroll
            for (int rr = 0; rr < 8; rr++) acc[rr] += xs[rr * 8 + r8][dd] * g;
        }
        __syncthreads();
    }
#pragma unroll
    for (int rr = 0; rr < 8; rr++) lg[rr * 8 + r8][e] = acc[rr];
    __syncthreads();

    int w = tid >> 5, lane = tid & 31;
    for (int ti = 0; ti < 8; ti++) {
        int tok = w * 8 + ti;
        float logit = lg[tok][lane];
        unsigned selmask = 0;
        float vals[TOPK]; int ids[TOPK];
#pragma unroll
        for (int k = 0; k < TOPK; k++) {
            float v = ((selmask >> lane) & 1u) ? -1e30f : logit;
            float bv = v; int bi = lane;
#pragma unroll
            for (int off = 16; off; off >>= 1) {
                float ov = __shfl_down_sync(0xffffffffu, bv, off);
                int   oi = __shfl_down_sync(0xffffffffu, bi, off);
                if (ov > bv || (ov == bv && oi < bi)) { bv = ov; bi = oi; }
            }
            bv = __shfl_sync(0xffffffffu, bv, 0);
            bi = __shfl_sync(0xffffffffu, bi, 0);
            vals[k] = bv; ids[k] = bi;
            selmask |= 1u << bi;
        }
        if (lane == 0) {
            float mx = vals[0], s = 0.f, wv[TOPK];
#pragma unroll
            for (int k = 0; k < TOPK; k++) { wv[k] = expf(vals[k] - mx); s += wv[k]; }
            float inv = 1.f / s;
            int t = t0 + tok;
#pragma unroll
            for (int k = 0; k < TOPK; k++) {
                g_weight_of[t * TOPK + k] = wv[k] * inv;
                g_expert_of[t * TOPK + k] = ids[k];
            }
        }
    }
}

// ============ fused histogram + prefix + tile map + scatter (launch #3) ============
__global__ __launch_bounds__(1024) void k_prefix_scatter() {
    __shared__ int cnt[NEXP], off_s[NEXP + 1], cur[NEXP];
    int tid = threadIdx.x;
    if (tid < NEXP) { cnt[tid] = 0; cur[tid] = 0; }
    __syncthreads();
    for (int i = tid; i < NROWS; i += 1024)
        atomicAdd(&cnt[g_expert_of[i]], 1);
    __syncthreads();
    if (tid < 32) {
        int c = (tid < NEXP) ? cnt[tid] : 0;
        int s = c;
#pragma unroll
        for (int off = 1; off < 32; off <<= 1) {
            int v = __shfl_up_sync(0xffffffffu, s, off);
            if (tid >= off) s += v;
        }
        if (tid < NEXP) off_s[tid + 1] = s;
        if (tid == 0) off_s[0] = 0;
    }
    __syncthreads();
    if (tid <= NEXP) g_off[tid] = off_s[tid];
    if (tid == 0) {
        int nt = 0;
        for (int e = 0; e < NEXP; e++) {
            int cc = cnt[e], base = off_s[e];
            for (int r = 0; r < cc; r += BM) {
                g_tile_expert[nt] = e;
                g_tile_row[nt] = base + r;
                nt++;
            }
        }
        g_num_tiles = nt;
    }
    for (int i = tid; i < NROWS; i += 1024) {
        int e = g_expert_of[i];
        int p = off_s[e] + atomicAdd(&cur[e], 1);
        g_row_token[p] = i >> 3;
        g_pos_of[i] = p;
    }
}

// ============ GEMM1 (launch #4): gate+up, 128M x 64N, 256thr, 2 CTAs/SM ============
// smem: A0@0 A1@8192 (h@0 l@4096, swizzled 32B rows)
//       B0@16384 B1@25088 (gate@0 up@4352; 272B k-rows; per n8: hi16B|lo16B)
// total 33792
__global__ __launch_bounds__(256, 2) void k_gemm1(const float* __restrict__ Wg,
                                                  const float* __restrict__ Wu) {
    int mt = blockIdx.y;
    if (mt >= g_num_tiles) return;
    int e = g_tile_expert[mt], row0 = g_tile_row[mt], row_end = g_off[e + 1];
    int n0 = blockIdx.x * 64;

    __shared__ __align__(128) char smem[33792];
    uint32_t sb = smem_u32(smem);
    int tid = threadIdx.x, wid = tid >> 5, lane = tid & 31;
    int wm0 = (wid >> 1) * 32, wn0 = (wid & 1) * 32;

    // A staging: thread owns (row, k-half)
    int r = tid >> 1, c2 = tid & 1;
    int gr = row0 + r; if (gr > NROWS - 1) gr = NROWS - 1;
    int tok = g_row_token[gr];
    const __nv_bfloat16* srcAh = g_Xh + (size_t)tok * DIM + c2 * 8;
    const __nv_bfloat16* srcAl = g_Xl + (size_t)tok * DIM + c2 * 8;
    uint32_t stA = r * 32 + ((c2 ^ ((r >> 2) & 1)) << 4);

    // W staging: thread owns (kind, kr, n8-group) = 8 floats
    int kind = tid >> 7, remw = tid & 127, kr = remw >> 3, gq = remw & 7;
    const float* gW = (kind ? Wu : Wg) + ((size_t)e * DIM + kr) * MDIM + n0 + gq * 8;
    uint32_t stB = kind * 4352 + kr * 272 + gq * 32;

    float accG[2][4][4] = {}, accU[2][4][4] = {};
    uint32_t aOff;
    { int rr = wm0 + (lane & 15), cc = lane >> 4;
      aOff = rr * 32 + ((cc ^ ((rr >> 2) & 1)) << 4); }
    uint32_t bT = ((lane & 7) + ((lane >> 3) & 1) * 8) * 272 + ((lane >> 4) & 1) * 16
                + wn0 * 4;   // n8-group stride is 32B -> wn0/8*32

    // prologue: chunk0 -> smem, chunk1 -> regs
    uint4 aRh = *(const uint4*)srcAh, aRl = *(const uint4*)srcAl;
    float4 w0 = *(const float4*)gW, w1 = *(const float4*)(gW + 4);
    *(uint4*)(smem + stA) = aRh;
    *(uint4*)(smem + 4096 + stA) = aRl;
    {
        uint2 h0, l0, h1, l1;
        split4pack_trunc(w0, h0, l0); split4pack_trunc(w1, h1, l1);
        *(uint4*)(smem + 16384 + stB)      = make_uint4(h0.x, h0.y, h1.x, h1.y);
        *(uint4*)(smem + 16384 + stB + 16) = make_uint4(l0.x, l0.y, l1.x, l1.y);
    }
    aRh = *(const uint4*)(srcAh + 16); aRl = *(const uint4*)(srcAl + 16);
    w0 = *(const float4*)(gW + (size_t)16 * MDIM);
    w1 = *(const float4*)(gW + (size_t)16 * MDIM + 4);

    const int NCH = DIM / 16;  // 128
    for (int kc = 0; kc < NCH; kc++) {
        int st = kc & 1;
        __syncthreads();
        if (kc + 1 < NCH) {
            uint32_t as = (st ^ 1) * 8192;
            *(uint4*)(smem + as + stA) = aRh;
            *(uint4*)(smem + as + 4096 + stA) = aRl;
            uint32_t bs = 16384 + (st ^ 1) * 8704;
            uint2 h0, l0, h1, l1;
            split4pack_trunc(w0, h0, l0); split4pack_trunc(w1, h1, l1);
            *(uint4*)(smem + bs + stB)      = make_uint4(h0.x, h0.y, h1.x, h1.y);
            *(uint4*)(smem + bs + stB + 16) = make_uint4(l0.x, l0.y, l1.x, l1.y);
        }
        if (kc + 2 < NCH) {
            int ko = (kc + 2) * 16;
            aRh = *(const uint4*)(srcAh + ko);
            aRl = *(const uint4*)(srcAl + ko);
            w0 = *(const float4*)(gW + (size_t)ko * MDIM);
            w1 = *(const float4*)(gW + (size_t)ko * MDIM + 4);
        }
        uint32_t aA = sb + st * 8192 + aOff;
        uint32_t aH0[4], aH1[4], aL0[4], aL1[4];
        LDSM4(aH0, aA); LDSM4(aH1, aA + 512);
        LDSM4(aL0, aA + 4096); LDSM4(aL1, aA + 4608);
        uint32_t bb = sb + 16384 + st * 8704 + bT;
#pragma unroll
        for (int g = 0; g < 4; g++) {
            uint32_t b[4];
            LDSM4T(b, bb + g * 32);           // gate: b01=hi, b23=lo
            MMA_BF16(accG[0][g], aH0, b[0], b[1]);
            MMA_BF16(accG[1][g], aH1, b[0], b[1]);
            MMA_BF16(accG[0][g], aL0, b[0], b[1]);
            MMA_BF16(accG[1][g], aL1, b[0], b[1]);
            MMA_BF16(accG[0][g], aH0, b[2], b[3]);
            MMA_BF16(accG[1][g], aH1, b[2], b[3]);
            LDSM4T(b, bb + 4352 + g * 32);    // up
            MMA_BF16(accU[0][g], aH0, b[0], b[1]);
            MMA_BF16(accU[1][g], aH1, b[0], b[1]);
            MMA_BF16(accU[0][g], aL0, b[0], b[1]);
            MMA_BF16(accU[1][g], aL1, b[0], b[1]);
            MMA_BF16(accU[0][g], aH0, b[2], b[3]);
            MMA_BF16(accU[1][g], aH1, b[2], b[3]);
        }
    }

    // epilogue: silu(g)*u -> split bf16
#pragma unroll
    for (int f = 0; f < 2; f++) {
        int rl = row0 + wm0 + f * 16 + (lane >> 2);
        int rh = rl + 8;
#pragma unroll
        for (int g = 0; g < 4; g++) {
            int c = n0 + wn0 + g * 8 + (lane & 3) * 2;
            float g0 = accG[f][g][0], g1 = accG[f][g][1];
            float g2 = accG[f][g][2], g3 = accG[f][g][3];
            float u0 = accU[f][g][0], u1 = accU[f][g][1];
            float u2 = accU[f][g][2], u3 = accU[f][g][3];
            float v0 = (g0 / (1.f + __expf(-g0))) * u0;
            float v1 = (g1 / (1.f + __expf(-g1))) * u1;
            float v2 = (g2 / (1.f + __expf(-g2))) * u2;
            float v3 = (g3 / (1.f + __expf(-g3))) * u3;
            __nv_bfloat16 h0, l0, h1, l1, h2, l2, h3, l3;
            split2(v0, h0, l0); split2(v1, h1, l1);
            split2(v2, h2, l2); split2(v3, h3, l3);
            if (rl < row_end) {
                *(uint32_t*)(g_Ih + (size_t)rl * MDIM + c) = pack2(h0, h1);
                *(uint32_t*)(g_Il + (size_t)rl * MDIM + c) = pack2(l0, l1);
            }
            if (rh < row_end) {
                *(uint32_t*)(g_Ih + (size_t)rh * MDIM + c) = pack2(h2, h3);
                *(uint32_t*)(g_Il + (size_t)rh * MDIM + c) = pack2(l2, l3);
            }
        }
    }
}

// ============ GEMM2 (launch #5): down, 128M x 64N, 256thr, 2 CTAs/SM ============
// smem: A0@0 A1@8192; B0@16384 B1@20736 (272B k-rows, hi|lo per n8); total 25088
__global__ __launch_bounds__(256, 2) void k_gemm2(const float* __restrict__ Wd) {
    int mt = blockIdx.y;
    if (mt >= g_num_tiles) return;
    int e = g_tile_expert[mt], row0 = g_tile_row[mt], row_end = g_off[e + 1];
    int n0 = blockIdx.x * 64;

    __shared__ __align__(128) char smem[25088];
    uint32_t sb = smem_u32(smem);
    int tid = threadIdx.x, wid = tid >> 5, lane = tid & 31;
    int wm0 = (wid >> 1) * 32, wn0 = (wid & 1) * 32;

    int r = tid >> 1, c2 = tid & 1;
    int gr = row0 + r; if (gr > NROWS - 1) gr = NROWS - 1;
    const __nv_bfloat16* srcAh = g_Ih + (size_t)gr * MDIM + c2 * 8;
    const __nv_bfloat16* srcAl = g_Il + (size_t)gr * MDIM + c2 * 8;
    uint32_t stA = r * 32 + ((c2 ^ ((r >> 2) & 1)) << 4);

    bool doW = tid < 128;
    int kr = tid >> 3, gq = tid & 7;
    const float* gW = Wd + ((size_t)e * MDIM + (doW ? kr : 0)) * DIM + n0 + gq * 8;
    uint32_t stB = kr * 272 + gq * 32;

    float acc[2][4][4] = {};
    uint32_t aOff;
    { int rr = wm0 + (lane & 15), cc = lane >> 4;
      aOff = rr * 32 + ((cc ^ ((rr >> 2) & 1)) << 4); }
    uint32_t bT = ((lane & 7) + ((lane >> 3) & 1) * 8) * 272 + ((lane >> 4) & 1) * 16
                + wn0 * 4;

    uint4 aRh = *(const uint4*)srcAh, aRl = *(const uint4*)srcAl;
    float4 w0, w1;
    if (doW) { w0 = *(const float4*)gW; w1 = *(const float4*)(gW + 4); }
    *(uint4*)(smem + stA) = aRh;
    *(uint4*)(smem + 4096 + stA) = aRl;
    if (doW) {
        uint2 h0, l0, h1, l1;
        split4pack_trunc(w0, h0, l0); split4pack_trunc(w1, h1, l1);
        *(uint4*)(smem + 16384 + stB)      = make_uint4(h0.x, h0.y, h1.x, h1.y);
        *(uint4*)(smem + 16384 + stB + 16) = make_uint4(l0.x, l0.y, l1.x, l1.y);
    }
    aRh = *(const uint4*)(srcAh + 16); aRl = *(const uint4*)(srcAl + 16);
    if (doW) {
        w0 = *(const float4*)(gW + (size_t)16 * DIM);
        w1 = *(const float4*)(gW + (size_t)16 * DIM + 4);
    }

    const int NCH = MDIM / 16;  // 48
    for (int kc = 0; kc < NCH; kc++) {
        int st = kc & 1;
        __syncthreads();
        if (kc + 1 < NCH) {
            uint32_t as = (st ^ 1) * 8192;
            *(uint4*)(smem + as + stA) = aRh;
            *(uint4*)(smem + as + 4096 + stA) = aRl;
            if (doW) {
                uint32_t bs = 16384 + (st ^ 1) * 4352;
                uint2 h0, l0, h1, l1;
                split4pack_trunc(w0, h0, l0); split4pack_trunc(w1, h1, l1);
                *(uint4*)(smem + bs + stB)      = make_uint4(h0.x, h0.y, h1.x, h1.y);
                *(uint4*)(smem + bs + stB + 16) = make_uint4(l0.x, l0.y, l1.x, l1.y);
            }
        }
        if (kc + 2 < NCH) {
            int ko = (kc + 2) * 16;
            aRh = *(const uint4*)(srcAh + ko);
            aRl = *(const uint4*)(srcAl + ko);
            if (doW) {
                w0 = *(const float4*)(gW + (size_t)ko * DIM);
                w1 = *(const float4*)(gW + (size_t)ko * DIM + 4);
            }
        }
        uint32_t aA = sb + st * 8192 + aOff;
        uint32_t aH0[4], aH1[4], aL0[4], aL1[4];
        LDSM4(aH0, aA); LDSM4(aH1, aA + 512);
        LDSM4(aL0, aA + 4096); LDSM4(aL1, aA + 4608);
        uint32_t bb = sb + 16384 + st * 4352 + bT;
#pragma unroll
        for (int g = 0; g < 4; g++) {
            uint32_t b[4];
            LDSM4T(b, bb + g * 32);   // b01=hi, b23=lo
            MMA_BF16(acc[0][g], aH0, b[0], b[1]);
            MMA_BF16(acc[1][g], aH1, b[0], b[1]);
            MMA_BF16(acc[0][g], aL0, b[0], b[1]);
            MMA_BF16(acc[1][g], aL1, b[0], b[1]);
            MMA_BF16(acc[0][g], aH0, b[2], b[3]);
            MMA_BF16(acc[1][g], aH1, b[2], b[3]);
        }
    }

#pragma unroll
    for (int f = 0; f < 2; f++) {
        int rl = row0 + wm0 + f * 16 + (lane >> 2);
        int rh = rl + 8;
#pragma unroll
        for (int g = 0; g < 4; g++) {
            int c = n0 + wn0 + g * 8 + (lane & 3) * 2;
            if (rl < row_end)
                *(float2*)(g_eout + (size_t)rl * DIM + c) = make_float2(acc[f][g][0], acc[f][g][1]);
            if (rh < row_end)
                *(float2*)(g_eout + (size_t)rh * DIM + c) = make_float2(acc[f][g][2], acc[f][g][3]);
        }
    }
}

// ============ combine (launch #6) ============
__global__ __launch_bounds__(256) void k_combine(float* __restrict__ out) {
    int t = blockIdx.x;
    __shared__ float w[TOPK];
    __shared__ int   ps[TOPK];
    if (threadIdx.x < TOPK) {
        w[threadIdx.x]  = g_weight_of[t * TOPK + threadIdx.x];
        ps[threadIdx.x] = g_pos_of[t * TOPK + threadIdx.x];
    }
    __syncthreads();
    for (int d = threadIdx.x; d < DIM; d += 256) {
        float s = 0.f;
#pragma unroll
        for (int k = 0; k < TOPK; k++)
            s += w[k] * g_eout[(size_t)ps[k] * DIM + d];
        out[(size_t)t * DIM + d] = s;
    }
}

// ============ launch ============
extern "C" void kernel_launch(void* const* d_in, const int* in_sizes, int n_in,
                              void* d_out, int out_size) {
    const float* x  = (const float*)d_in[0];
    const float* gk = (const float*)d_in[1];
    const float* wg = (const float*)d_in[2];
    const float* wu = (const float*)d_in[3];
    const float* wd = (const float*)d_in[4];
    float* out = (float*)d_out;

    k_convert_x<<<TOKENS, 256>>>(x);
    k_router<<<TOKENS / 64, 256>>>(x, gk);
    k_prefix_scatter<<<1, 1024>>>();
    k_gemm1<<<dim3(MDIM / 64, MAX_TILES), 256>>>(wg, wu);
    k_gemm2<<<dim3(DIM / 64, MAX_TILES), 256>>>(wd);
    k_combine<<<TOKENS, 256>>>(out);
}

// round 17
// speedup vs baseline: 1.0219x; 1.0219x over previous
#include <cuda_runtime.h>
#include <cuda_bf16.h>
#include <stdint.h>
#include <math.h>

#define TOKENS 4096
#define DIM    2048
#define NEXP   32
#define TOPK   8
#define MDIM   768
#define NROWS  (TOKENS*TOPK)
#define BM     128
#define MAX_TILES 288

__device__ __forceinline__ uint32_t smem_u32(const void* p) {
    uint32_t a;
    asm("{ .reg .u64 t; cvta.to.shared.u64 t, %1; cvt.u32.u64 %0, t; }" : "=r"(a) : "l"(p));
    return a;
}

#define LDSM4(r, addr) \
    asm volatile("ldmatrix.sync.aligned.m8n8.x4.shared.b16 {%0,%1,%2,%3}, [%4];" \
        : "=r"((r)[0]), "=r"((r)[1]), "=r"((r)[2]), "=r"((r)[3]) : "r"(addr))

#define LDSM4T(r, addr) \
    asm volatile("ldmatrix.sync.aligned.m8n8.x4.trans.shared.b16 {%0,%1,%2,%3}, [%4];" \
        : "=r"((r)[0]), "=r"((r)[1]), "=r"((r)[2]), "=r"((r)[3]) : "r"(addr))

#define MMA_BF16(d, a, b0v, b1v) \
    asm volatile("mma.sync.aligned.m16n8k16.row.col.f32.bf16.bf16.f32 " \
        "{%0,%1,%2,%3},{%4,%5,%6,%7},{%8,%9},{%0,%1,%2,%3};" \
        : "+f"((d)[0]), "+f"((d)[1]), "+f"((d)[2]), "+f"((d)[3]) \
        : "r"((a)[0]), "r"((a)[1]), "r"((a)[2]), "r"((a)[3]), "r"(b0v), "r"(b1v))

__device__ __forceinline__ void split2(float v, __nv_bfloat16& h, __nv_bfloat16& l) {
    h = __float2bfloat16(v);
    l = __float2bfloat16(v - __bfloat162float(h));
}
__device__ __forceinline__ uint32_t pack2(__nv_bfloat16 a, __nv_bfloat16 b) {
    __nv_bfloat162 t(a, b);
    return *(uint32_t*)&t;
}
__device__ __forceinline__ void split4pack(float4 v, uint2& hh, uint2& ll) {
    __nv_bfloat16 h0, h1, h2, h3, l0, l1, l2, l3;
    split2(v.x, h0, l0); split2(v.y, h1, l1);
    split2(v.z, h2, l2); split2(v.w, h3, l3);
    hh = make_uint2(pack2(h0, h1), pack2(h2, h3));
    ll = make_uint2(pack2(l0, l1), pack2(l2, l3));
}
// Truncation split (weights): hi = top-16 bits, lo = RN bf16 of residual
__device__ __forceinline__ void split4pack_trunc(float4 v, uint2& hh, uint2& ll) {
    uint32_t x0 = __float_as_uint(v.x), x1 = __float_as_uint(v.y);
    uint32_t x2 = __float_as_uint(v.z), x3 = __float_as_uint(v.w);
    hh.x = __byte_perm(x0, x1, 0x7632);
    hh.y = __byte_perm(x2, x3, 0x7632);
    float l0 = v.x - __uint_as_float(x0 & 0xffff0000u);
    float l1 = v.y - __uint_as_float(x1 & 0xffff0000u);
    float l2 = v.z - __uint_as_float(x2 & 0xffff0000u);
    float l3 = v.w - __uint_as_float(x3 & 0xffff0000u);
    uint32_t p0, p1;
    asm("cvt.rn.bf16x2.f32 %0, %1, %2;" : "=r"(p0) : "f"(l1), "f"(l0));
    asm("cvt.rn.bf16x2.f32 %0, %1, %2;" : "=r"(p1) : "f"(l3), "f"(l2));
    ll = make_uint2(p0, p1);
}

// ============ device scratch (~402MB, proven budget) ============
__device__ int   g_off[NEXP + 1];
__device__ int   g_expert_of[NROWS];
__device__ float g_weight_of[NROWS];
__device__ int   g_row_token[NROWS];
__device__ int   g_pos_of[NROWS];
__device__ int   g_tile_expert[MAX_TILES];
__device__ int   g_tile_row[MAX_TILES];
__device__ int   g_num_tiles;
__device__ __nv_bfloat16 g_Xh[(size_t)TOKENS * DIM];
__device__ __nv_bfloat16 g_Xl[(size_t)TOKENS * DIM];
__device__ __nv_bfloat16 g_Ih[(size_t)NROWS * MDIM];
__device__ __nv_bfloat16 g_Il[(size_t)NROWS * MDIM];
__device__ float g_eout[(size_t)NROWS * DIM];

// ============ token fp32 -> split bf16 (launch #1) ============
__global__ __launch_bounds__(256) void k_convert_x(const float* __restrict__ x) {
    int t = blockIdx.x;
    const float4* src = (const float4*)(x + (size_t)t * DIM);
#pragma unroll
    for (int i = 0; i < 2; i++) {
        int idx = threadIdx.x + i * 256;
        uint2 hh, ll;
        split4pack(src[idx], hh, ll);
        *(uint2*)(g_Xh + (size_t)t * DIM + idx * 4) = hh;
        *(uint2*)(g_Xl + (size_t)t * DIM + idx * 4) = ll;
    }
}

// ============ router (launch #2) ============
__global__ __launch_bounds__(256) void k_router(const float* __restrict__ x,
                                                const float* __restrict__ gk) {
    __shared__ float xs[64][64];
    __shared__ float gs[64][32];
    __shared__ float lg[64][32];
    int tid = threadIdx.x, t0 = blockIdx.x * 64, e = tid & 31, r8 = tid >> 5;
    float acc[8];
#pragma unroll
    for (int i = 0; i < 8; i++) acc[i] = 0.f;
    for (int d0 = 0; d0 < DIM; d0 += 64) {
#pragma unroll
        for (int i = 0; i < 4; i++) {
            int f = tid + i * 256, row = f >> 4, dv = f & 15;
            *(float4*)&xs[row][dv * 4] =
                *(const float4*)(x + (size_t)(t0 + row) * DIM + d0 + dv * 4);
        }
#pragma unroll
        for (int i = 0; i < 2; i++) {
            int f = tid + i * 256, dd = f >> 3, ev = f & 7;
            *(float4*)&gs[dd][ev * 4] =
                *(const float4*)(gk + (size_t)(d0 + dd) * NEXP + ev * 4);
        }
        __syncthreads();
#pragma unroll 8
        for (int dd = 0; dd < 64; dd++) {
            float g = gs[dd][e];
#pragma unroll
            for (int rr = 0; rr < 8; rr++) acc[rr] += xs[rr * 8 + r8][dd] * g;
        }
        __syncthreads();
    }
#pragma unroll
    for (int rr = 0; rr < 8; rr++) lg[rr * 8 + r8][e] = acc[rr];
    __syncthreads();

    int w = tid >> 5, lane = tid & 31;
    for (int ti = 0; ti < 8; ti++) {
        int tok = w * 8 + ti;
        float logit = lg[tok][lane];
        unsigned selmask = 0;
        float vals[TOPK]; int ids[TOPK];
#pragma unroll
        for (int k = 0; k < TOPK; k++) {
            float v = ((selmask >> lane) & 1u) ? -1e30f : logit;
            float bv = v; int bi = lane;
#pragma unroll
            for (int off = 16; off; off >>= 1) {
                float ov = __shfl_down_sync(0xffffffffu, bv, off);
                int   oi = __shfl_down_sync(0xffffffffu, bi, off);
                if (ov > bv || (ov == bv && oi < bi)) { bv = ov; bi = oi; }
            }
            bv = __shfl_sync(0xffffffffu, bv, 0);
            bi = __shfl_sync(0xffffffffu, bi, 0);
            vals[k] = bv; ids[k] = bi;
            selmask |= 1u << bi;
        }
        if (lane == 0) {
            float mx = vals[0], s = 0.f, wv[TOPK];
#pragma unroll
            for (int k = 0; k < TOPK; k++) { wv[k] = expf(vals[k] - mx); s += wv[k]; }
            float inv = 1.f / s;
            int t = t0 + tok;
#pragma unroll
            for (int k = 0; k < TOPK; k++) {
                g_weight_of[t * TOPK + k] = wv[k] * inv;
                g_expert_of[t * TOPK + k] = ids[k];
            }
        }
    }
}

// ============ fused histogram + prefix + tile map + scatter (launch #3) ============
__global__ __launch_bounds__(1024) void k_prefix_scatter() {
    __shared__ int cnt[NEXP], off_s[NEXP + 1], cur[NEXP];
    int tid = threadIdx.x;
    if (tid < NEXP) { cnt[tid] = 0; cur[tid] = 0; }
    __syncthreads();
    for (int i = tid; i < NROWS; i += 1024)
        atomicAdd(&cnt[g_expert_of[i]], 1);
    __syncthreads();
    if (tid < 32) {
        int c = (tid < NEXP) ? cnt[tid] : 0;
        int s = c;
#pragma unroll
        for (int off = 1; off < 32; off <<= 1) {
            int v = __shfl_up_sync(0xffffffffu, s, off);
            if (tid >= off) s += v;
        }
        if (tid < NEXP) off_s[tid + 1] = s;
        if (tid == 0) off_s[0] = 0;
    }
    __syncthreads();
    if (tid <= NEXP) g_off[tid] = off_s[tid];
    if (tid == 0) {
        int nt = 0;
        for (int e = 0; e < NEXP; e++) {
            int cc = cnt[e], base = off_s[e];
            for (int r = 0; r < cc; r += BM) {
                g_tile_expert[nt] = e;
                g_tile_row[nt] = base + r;
                nt++;
            }
        }
        g_num_tiles = nt;
    }
    for (int i = tid; i < NROWS; i += 1024) {
        int e = g_expert_of[i];
        int p = off_s[e] + atomicAdd(&cur[e], 1);
        g_row_token[p] = i >> 3;
        g_pos_of[i] = p;
    }
}

// ============ GEMM1 (launch #4): gate+up, 128M x 96N, interleaved hi|lo B + swpipe ============
// smem: A0@0 A1@8192 (h@0 l@4096, swizzled 32B rows)
//       B@16384 + st*12800: gate@0 (16 rows x 400B = 12 groups x (hi16|lo16) + pad), up@6400
// total 41984
__global__ __launch_bounds__(256) void k_gemm1(const float* __restrict__ Wg,
                                               const float* __restrict__ Wu) {
    int mt = blockIdx.y;
    if (mt >= g_num_tiles) return;
    int e = g_tile_expert[mt], row0 = g_tile_row[mt], row_end = g_off[e + 1];
    int n0 = blockIdx.x * 96;

    __shared__ __align__(128) char smem[41984];
    uint32_t sb = smem_u32(smem);
    int tid = threadIdx.x, wid = tid >> 5, lane = tid & 31;
    int wm0 = (wid >> 1) * 32, nio = wid & 1;

    // A staging
    int r = tid >> 1, c2 = tid & 1;
    int gr = row0 + r; if (gr > NROWS - 1) gr = NROWS - 1;
    int tok = g_row_token[gr];
    const __nv_bfloat16* srcAh = g_Xh + (size_t)tok * DIM + c2 * 8;
    const __nv_bfloat16* srcAl = g_Xl + (size_t)tok * DIM + c2 * 8;
    uint32_t stA = r * 32 + ((c2 ^ ((r >> 2) & 1)) << 4);

    // W staging: 3 float4/thread (2 mats x 16k x 24 float4)
    const float* gW[3]; uint32_t stB[3];
#pragma unroll
    for (int i = 0; i < 3; i++) {
        int s = tid + i * 256;
        int mat = s / 384, rem = s - mat * 384;
        int kr = rem / 24, nq = rem - kr * 24;
        const float* W = mat ? Wu : Wg;
        gW[i] = W + ((size_t)e * DIM + kr) * MDIM + n0 + nq * 4;
        stB[i] = mat * 6400 + kr * 400 + (nq >> 1) * 32 + (nq & 1) * 8;
    }

    float accG[2][6][4] = {}, accU[2][6][4] = {};
    uint32_t aOff;
    { int rr = wm0 + (lane & 15), cc = lane >> 4;
      aOff = rr * 32 + ((cc ^ ((rr >> 2) & 1)) << 4); }
    uint32_t bT = ((lane & 7) + ((lane >> 3) & 1) * 8) * 400 + ((lane >> 4) & 1) * 16;

    // prologue: chunk0 store, chunk1 regs
    uint4 aRh = *(const uint4*)srcAh, aRl = *(const uint4*)srcAl;
    float4 wR[3];
#pragma unroll
    for (int i = 0; i < 3; i++) wR[i] = *(const float4*)gW[i];
    *(uint4*)(smem + stA) = aRh;
    *(uint4*)(smem + 4096 + stA) = aRl;
#pragma unroll
    for (int i = 0; i < 3; i++) {
        uint2 hh, ll;
        split4pack_trunc(wR[i], hh, ll);
        *(uint2*)(smem + 16384 + stB[i]) = hh;
        *(uint2*)(smem + 16384 + stB[i] + 16) = ll;
    }
    aRh = *(const uint4*)(srcAh + 16); aRl = *(const uint4*)(srcAl + 16);
#pragma unroll
    for (int i = 0; i < 3; i++) wR[i] = *(const float4*)(gW[i] + (size_t)16 * MDIM);

    const int NCH = DIM / 16;  // 128
    for (int kc = 0; kc < NCH; kc++) {
        int st = kc & 1;
        __syncthreads();
        if (kc + 1 < NCH) {
            uint32_t as = (st ^ 1) * 8192;
            *(uint4*)(smem + as + stA) = aRh;
            *(uint4*)(smem + as + 4096 + stA) = aRl;
            uint32_t bs = 16384 + (st ^ 1) * 12800;
#pragma unroll
            for (int i = 0; i < 3; i++) {
                uint2 hh, ll;
                split4pack_trunc(wR[i], hh, ll);
                *(uint2*)(smem + bs + stB[i]) = hh;
                *(uint2*)(smem + bs + stB[i] + 16) = ll;
            }
        }
        if (kc + 2 < NCH) {
            int ko = (kc + 2) * 16;
            aRh = *(const uint4*)(srcAh + ko);
            aRl = *(const uint4*)(srcAl + ko);
#pragma unroll
            for (int i = 0; i < 3; i++)
                wR[i] = *(const float4*)(gW[i] + (size_t)ko * MDIM);
        }
        uint32_t aA = sb + st * 8192 + aOff;
        uint32_t aH0[4], aH1[4], aL0[4], aL1[4];
        LDSM4(aH0, aA); LDSM4(aH1, aA + 512);
        LDSM4(aL0, aA + 4096); LDSM4(aL1, aA + 4608);
        uint32_t bbG = sb + 16384 + st * 12800 + bT;
        uint32_t bbU = bbG + 6400;
        // software-pipelined B fragments (double buffered)
        uint32_t bg[2][4], bu[2][4];
        LDSM4T(bg[0], bbG + nio * 32);
        LDSM4T(bu[0], bbU + nio * 32);
#pragma unroll
        for (int g = 0; g < 6; g++) {
            int cur = g & 1, nxt = cur ^ 1;
            if (g < 5) {
                uint32_t go = (2 * (g + 1) + nio) * 32;
                LDSM4T(bg[nxt], bbG + go);
                LDSM4T(bu[nxt], bbU + go);
            }
            MMA_BF16(accG[0][g], aH0, bg[cur][0], bg[cur][1]);
            MMA_BF16(accG[1][g], aH1, bg[cur][0], bg[cur][1]);
            MMA_BF16(accG[0][g], aL0, bg[cur][0], bg[cur][1]);
            MMA_BF16(accG[1][g], aL1, bg[cur][0], bg[cur][1]);
            MMA_BF16(accG[0][g], aH0, bg[cur][2], bg[cur][3]);
            MMA_BF16(accG[1][g], aH1, bg[cur][2], bg[cur][3]);
            MMA_BF16(accU[0][g], aH0, bu[cur][0], bu[cur][1]);
            MMA_BF16(accU[1][g], aH1, bu[cur][0], bu[cur][1]);
            MMA_BF16(accU[0][g], aL0, bu[cur][0], bu[cur][1]);
            MMA_BF16(accU[1][g], aL1, bu[cur][0], bu[cur][1]);
            MMA_BF16(accU[0][g], aH0, bu[cur][2], bu[cur][3]);
            MMA_BF16(accU[1][g], aH1, bu[cur][2], bu[cur][3]);
        }
    }

    // epilogue: silu(g)*u -> split bf16
#pragma unroll
    for (int f = 0; f < 2; f++) {
        int rl = row0 + wm0 + f * 16 + (lane >> 2);
        int rh = rl + 8;
#pragma unroll
        for (int g = 0; g < 6; g++) {
            int c = n0 + (2 * g + nio) * 8 + (lane & 3) * 2;
            float g0 = accG[f][g][0], g1 = accG[f][g][1];
            float g2 = accG[f][g][2], g3 = accG[f][g][3];
            float u0 = accU[f][g][0], u1 = accU[f][g][1];
            float u2 = accU[f][g][2], u3 = accU[f][g][3];
            float v0 = (g0 / (1.f + __expf(-g0))) * u0;
            float v1 = (g1 / (1.f + __expf(-g1))) * u1;
            float v2 = (g2 / (1.f + __expf(-g2))) * u2;
            float v3 = (g3 / (1.f + __expf(-g3))) * u3;
            __nv_bfloat16 h0, l0, h1, l1, h2, l2, h3, l3;
            split2(v0, h0, l0); split2(v1, h1, l1);
            split2(v2, h2, l2); split2(v3, h3, l3);
            if (rl < row_end) {
                *(uint32_t*)(g_Ih + (size_t)rl * MDIM + c) = pack2(h0, h1);
                *(uint32_t*)(g_Il + (size_t)rl * MDIM + c) = pack2(l0, l1);
            }
            if (rh < row_end) {
                *(uint32_t*)(g_Ih + (size_t)rh * MDIM + c) = pack2(h2, h3);
                *(uint32_t*)(g_Il + (size_t)rh * MDIM + c) = pack2(l2, l3);
            }
        }
    }
}

// ============ GEMM2 (launch #5): down, 128M x 128N, interleaved B + swpipe ============
// smem: A0@0 A1@8192; B@16384 + st*8448 (16 rows x 528B; per n8: hi16|lo16); total 33280
__global__ __launch_bounds__(256) void k_gemm2(const float* __restrict__ Wd) {
    int mt = blockIdx.y;
    if (mt >= g_num_tiles) return;
    int e = g_tile_expert[mt], row0 = g_tile_row[mt], row_end = g_off[e + 1];
    int n0 = blockIdx.x * 128;

    __shared__ __align__(128) char smem[33280];
    uint32_t sb = smem_u32(smem);
    int tid = threadIdx.x, wid = tid >> 5, lane = tid & 31;
    int wm0 = (wid >> 1) * 32, nio = wid & 1;

    int r = tid >> 1, c2 = tid & 1;
    int gr = row0 + r; if (gr > NROWS - 1) gr = NROWS - 1;
    const __nv_bfloat16* srcAh = g_Ih + (size_t)gr * MDIM + c2 * 8;
    const __nv_bfloat16* srcAl = g_Il + (size_t)gr * MDIM + c2 * 8;
    uint32_t stA = r * 32 + ((c2 ^ ((r >> 2) & 1)) << 4);

    const float* gW[2]; uint32_t stB[2];
#pragma unroll
    for (int i = 0; i < 2; i++) {
        int s = tid + i * 256;
        int kr = s >> 5, nq = s & 31;
        gW[i] = Wd + ((size_t)e * MDIM + kr) * DIM + n0 + nq * 4;
        stB[i] = kr * 528 + (nq >> 1) * 32 + (nq & 1) * 8;
    }

    float acc[2][8][4] = {};
    uint32_t aOff;
    { int rr = wm0 + (lane & 15), cc = lane >> 4;
      aOff = rr * 32 + ((cc ^ ((rr >> 2) & 1)) << 4); }
    uint32_t bT = ((lane & 7) + ((lane >> 3) & 1) * 8) * 528 + ((lane >> 4) & 1) * 16;

    uint4 aRh = *(const uint4*)srcAh, aRl = *(const uint4*)srcAl;
    float4 wR[2];
#pragma unroll
    for (int i = 0; i < 2; i++) wR[i] = *(const float4*)gW[i];
    *(uint4*)(smem + stA) = aRh;
    *(uint4*)(smem + 4096 + stA) = aRl;
#pragma unroll
    for (int i = 0; i < 2; i++) {
        uint2 hh, ll;
        split4pack_trunc(wR[i], hh, ll);
        *(uint2*)(smem + 16384 + stB[i]) = hh;
        *(uint2*)(smem + 16384 + stB[i] + 16) = ll;
    }
    aRh = *(const uint4*)(srcAh + 16); aRl = *(const uint4*)(srcAl + 16);
#pragma unroll
    for (int i = 0; i < 2; i++) wR[i] = *(const float4*)(gW[i] + (size_t)16 * DIM);

    const int NCH = MDIM / 16;  // 48
    for (int kc = 0; kc < NCH; kc++) {
        int st = kc & 1;
        __syncthreads();
        if (kc + 1 < NCH) {
            uint32_t as = (st ^ 1) * 8192;
            *(uint4*)(smem + as + stA) = aRh;
            *(uint4*)(smem + as + 4096 + stA) = aRl;
            uint32_t bs = 16384 + (st ^ 1) * 8448;
#pragma unroll
            for (int i = 0; i < 2; i++) {
                uint2 hh, ll;
                split4pack_trunc(wR[i], hh, ll);
                *(uint2*)(smem + bs + stB[i]) = hh;
                *(uint2*)(smem + bs + stB[i] + 16) = ll;
            }
        }
        if (kc + 2 < NCH) {
            int ko = (kc + 2) * 16;
            aRh = *(const uint4*)(srcAh + ko);
            aRl = *(const uint4*)(srcAl + ko);
#pragma unroll
            for (int i = 0; i < 2; i++)
                wR[i] = *(const float4*)(gW[i] + (size_t)ko * DIM);
        }
        uint32_t aA = sb + st * 8192 + aOff;
        uint32_t aH0[4], aH1[4], aL0[4], aL1[4];
        LDSM4(aH0, aA); LDSM4(aH1, aA + 512);
        LDSM4(aL0, aA + 4096); LDSM4(aL1, aA + 4608);
        uint32_t bb = sb + 16384 + st * 8448 + bT;
        uint32_t bf[2][4];
        LDSM4T(bf[0], bb + (2 * nio) * 32);
#pragma unroll
        for (int q = 0; q < 8; q++) {
            int cur = q & 1, nxt = cur ^ 1;
            if (q < 7) {
                int q1 = q + 1;
                uint32_t go = (4 * (q1 >> 1) + 2 * nio + (q1 & 1)) * 32;
                LDSM4T(bf[nxt], bb + go);
            }
            MMA_BF16(acc[0][q], aH0, bf[cur][0], bf[cur][1]);
            MMA_BF16(acc[1][q], aH1, bf[cur][0], bf[cur][1]);
            MMA_BF16(acc[0][q], aL0, bf[cur][0], bf[cur][1]);
            MMA_BF16(acc[1][q], aL1, bf[cur][0], bf[cur][1]);
            MMA_BF16(acc[0][q], aH0, bf[cur][2], bf[cur][3]);
            MMA_BF16(acc[1][q], aH1, bf[cur][2], bf[cur][3]);
        }
    }

#pragma unroll
    for (int f = 0; f < 2; f++) {
        int rl = row0 + wm0 + f * 16 + (lane >> 2);
        int rh = rl + 8;
#pragma unroll
        for (int q = 0; q < 8; q++) {
            int c = n0 + (4 * (q >> 1) + 2 * nio + (q & 1)) * 8 + (lane & 3) * 2;
            if (rl < row_end)
                *(float2*)(g_eout + (size_t)rl * DIM + c) = make_float2(acc[f][q][0], acc[f][q][1]);
            if (rh < row_end)
                *(float2*)(g_eout + (size_t)rh * DIM + c) = make_float2(acc[f][q][2], acc[f][q][3]);
        }
    }
}

// ============ combine (launch #6) ============
__global__ __launch_bounds__(256) void k_combine(float* __restrict__ out) {
    int t = blockIdx.x;
    __shared__ float w[TOPK];
    __shared__ int   ps[TOPK];
    if (threadIdx.x < TOPK) {
        w[threadIdx.x]  = g_weight_of[t * TOPK + threadIdx.x];
        ps[threadIdx.x] = g_pos_of[t * TOPK + threadIdx.x];
    }
    __syncthreads();
    for (int d = threadIdx.x; d < DIM; d += 256) {
        float s = 0.f;
#pragma unroll
        for (int k = 0; k < TOPK; k++)
            s += w[k] * g_eout[(size_t)ps[k] * DIM + d];
        out[(size_t)t * DIM + d] = s;
    }
}

// ============ launch ============
extern "C" void kernel_launch(void* const* d_in, const int* in_sizes, int n_in,
                              void* d_out, int out_size) {
    const float* x  = (const float*)d_in[0];
    const float* gk = (const float*)d_in[1];
    const float* wg = (const float*)d_in[2];
    const float* wu = (const float*)d_in[3];
    const float* wd = (const float*)d_in[4];
    float* out = (float*)d_out;

    k_convert_x<<<TOKENS, 256>>>(x);
    k_router<<<TOKENS / 64, 256>>>(x, gk);
    k_prefix_scatter<<<1, 1024>>>();
    k_gemm1<<<dim3(MDIM / 96, MAX_TILES), 256>>>(wg, wu);
    k_gemm2<<<dim3(DIM / 128, MAX_TILES), 256>>>(wd);
    k_combine<<<TOKENS, 256>>>(out);
}